// round 13
// baseline (speedup 1.0000x reference)
#include <cuda_runtime.h>
#include <cstdint>

#define BROWS 32768
#define D0 1024
#define D1 512
#define D2 256

#define CAP 480           // smem-compacted dynamic elems per row (max expected ~430)
#define PAIRS_REG 13      // f32x2 pairs per lane, 16 lanes/row -> 416 elems in regs
#define REG_ELEMS 416
#define K_OVF 4           // per-lane register overflow slots beyond CAP
#define EPSC 1e-6f

// Small precomputed tables
__device__ __align__(16) float g_s0[D0];
__device__ __align__(16) float g_s1[D1];
__device__ __align__(16) float g_s1s[D1];
__device__ __align__(16) float2 g_PQ[D1 + 1];

// Dynamic smem layout (floats):
//   [s1s 512][PQ float2 x 513 = 1026 floats][pad 2][pairs: 16 rows x (w CAP | mt CAP)]
#define SM_S1S   0
#define SM_PQ    512          // float2 base (byte offset 2048, 8B aligned)
#define SM_PAIRS 1540
#define SM_FLOATS (SM_PAIRS + 16 * 2 * CAP)   // 16900 floats = 67600 bytes

// ---------------------------------------------------------------------------
// Packed f32x2 helpers
// ---------------------------------------------------------------------------
__device__ __forceinline__ unsigned long long ffma2(unsigned long long a,
                                                    unsigned long long b,
                                                    unsigned long long c) {
    unsigned long long d;
    asm("fma.rn.f32x2 %0, %1, %2, %3;" : "=l"(d) : "l"(a), "l"(b), "l"(c));
    return d;
}
__device__ __forceinline__ unsigned long long fadd2(unsigned long long a,
                                                    unsigned long long b) {
    unsigned long long d;
    asm("add.rn.f32x2 %0, %1, %2;" : "=l"(d) : "l"(a), "l"(b));
    return d;
}
__device__ __forceinline__ unsigned long long pack2(float lo, float hi) {
    unsigned long long d;
    asm("mov.b64 %0, {%1, %2};" : "=l"(d) : "f"(lo), "f"(hi));
    return d;
}
__device__ __forceinline__ float2 unpack2(unsigned long long v) {
    float2 r;
    asm("mov.b64 {%0, %1}, %2;" : "=f"(r.x), "=f"(r.y) : "l"(v));
    return r;
}
__device__ __forceinline__ float warp_sum(float s) {
    #pragma unroll
    for (int o = 16; o; o >>= 1) s += __shfl_xor_sync(0xFFFFFFFFu, s, o);
    return s;
}
__device__ __forceinline__ float rcp_approx(float v) {
    float r;
    asm("rcp.approx.f32 %0, %1;" : "=f"(r) : "f"(v));
    return r;
}

// ---------------------------------------------------------------------------
// Kernel 1: row sums of W0 and W1
// ---------------------------------------------------------------------------
__global__ void rowsum_kernel(const float* __restrict__ W0,
                              const float* __restrict__ W1) {
    int warp = (blockIdx.x * blockDim.x + threadIdx.x) >> 5;
    int lane = threadIdx.x & 31;
    if (warp < D0) {
        const float* row = W0 + (size_t)warp * D1;
        float s = 0.0f;
        #pragma unroll
        for (int k = 0; k < D1 / 32; k++) s += row[lane + 32 * k];
        s = warp_sum(s);
        if (lane == 0) g_s0[warp] = s;
    } else if (warp < D0 + D1) {
        int j = warp - D0;
        const float* row = W1 + (size_t)j * D2;
        float s = 0.0f;
        #pragma unroll
        for (int k = 0; k < D2 / 32; k++) s += row[lane + 32 * k];
        s = warp_sum(s);
        if (lane == 0) g_s1[j] = s;
    }
}

// ---------------------------------------------------------------------------
// Kernel 1b: sort s1 + prefix tables -> g_s1s, g_PQ
//   cur1(a0,a1) = a0*P[i] + a1*Q[i] with i = #{j : a1*s1s[j] <= a0}
// ---------------------------------------------------------------------------
__global__ void sort_prefix_kernel() {
    __shared__ float a[D1];
    __shared__ float b[D1];
    int tid = threadIdx.x;

    a[tid] = g_s1[tid];
    __syncthreads();
    for (int k = 2; k <= D1; k <<= 1) {
        for (int j = k >> 1; j > 0; j >>= 1) {
            int ixj = tid ^ j;
            if (ixj > tid) {
                bool up = ((tid & k) == 0);
                float x = a[tid], y = a[ixj];
                if ((x > y) == up) { a[tid] = y; a[ixj] = x; }
            }
            __syncthreads();
        }
    }
    float v = a[tid];
    for (int off = 1; off < D1; off <<= 1) {
        b[tid] = v;
        __syncthreads();
        if (tid >= off) v += b[tid - off];
        __syncthreads();
    }
    b[tid] = v;
    __syncthreads();

    g_s1s[tid] = a[tid];
    float ST = b[D1 - 1];
    for (int i = tid; i <= D1; i += D1) {
        float Si = (i == 0) ? 0.0f : b[i - 1];
        g_PQ[i] = make_float2((float)(2 * i - D1) * (1.0f / 256.0f),
                              (ST - 2.0f * Si) * (1.0f / 256.0f));
    }
}

// ---------------------------------------------------------------------------
// Kernel 2: fused preprocessing + SNN time loop.
// 256 threads / 8 warps / 16 rows per block. 16 lanes per row, 2 rows per warp.
// Layer-1 search is SPECULATED for both spike outcomes of layer 0, so its
// ~170-cycle chain overlaps the layer-0 reduction instead of following it.
// ---------------------------------------------------------------------------
__global__ __launch_bounds__(256, 3)
void snn_kernel(const float* __restrict__ x,
                const int* __restrict__ ts_ptr,
                float* __restrict__ out) {
    extern __shared__ float sm[];
    float2* pq_sm = reinterpret_cast<float2*>(sm + SM_PQ);

    const int warp = threadIdx.x >> 5;
    const int lane = threadIdx.x & 31;
    const int half = lane >> 4;          // 0 = row A, 1 = row B
    const int r    = lane & 15;          // lane index within the row group
    const int bufrow = warp * 2 + half;  // 0..15
    const int row  = blockIdx.x * 16 + bufrow;
    const unsigned halfmask = half ? 0xFFFF0000u : 0x0000FFFFu;
    const int tsteps = ts_ptr[0];

    float* wb = sm + SM_PAIRS + bufrow * (2 * CAP);
    float* mb = wb + CAP;

    // Load lookup tables
    for (int i = threadIdx.x; i < D1; i += 256) sm[SM_S1S + i] = g_s1s[i];
    for (int i = threadIdx.x; i <= D1; i += 256) pq_sm[i] = g_PQ[i];

    // ---- Pass 1: classify 64 elements per lane; accumulate C, D; flag dynamics ----
    const float4* xrow4 = reinterpret_cast<const float4*>(x + (size_t)row * D0);
    const float4* s04   = reinterpret_cast<const float4*>(g_s0);

    float C = 0.0f, Dv = 0.0f;
    unsigned long long flags = 0ULL;
    int cnt_lane = 0;

    for (int i = 0; i < 16; i++) {
        float4 xv = xrow4[r + 16 * i];
        float4 sv = __ldg(&s04[r + 16 * i]);
        const float* xp = &xv.x;
        const float* sp = &sv.x;
        #pragma unroll
        for (int k = 0; k < 4; k++) {
            float s = sp[k], xx = xp[k];
            float w = fabsf(s);
            float t = (s < 0.0f) ? -xx : xx;
            if (t < -EPSC * w)             { C -= t; Dv += w; }
            else if (t > (1.0f + EPSC) * w){ C += t; Dv -= w; }
            else { flags |= 1ULL << (i * 4 + k); cnt_lane++; }
        }
    }
    #pragma unroll
    for (int o = 8; o; o >>= 1) {
        C  += __shfl_xor_sync(0xFFFFFFFFu, C,  o, 16);
        Dv += __shfl_xor_sync(0xFFFFFFFFu, Dv, o, 16);
    }
    int incl = cnt_lane;
    #pragma unroll
    for (int o = 1; o < 16; o <<= 1) {
        int n = __shfl_up_sync(0xFFFFFFFFu, incl, o, 16);
        if (r >= o) incl += n;
    }
    int pos = incl - cnt_lane;
    int cnt = __shfl_sync(0xFFFFFFFFu, incl, 15, 16);

    // ---- Pass 2: write compacted (w, mt) into the row buffer ----
    float ovf_w[K_OVF], ovf_m[K_OVF];
    int novf = 0;
    for (int i = 0; i < 16; i++) {
        if (!((flags >> (i * 4)) & 0xFULL)) continue;
        float4 xv = xrow4[r + 16 * i];
        float4 sv = __ldg(&s04[r + 16 * i]);
        const float* xp = &xv.x;
        const float* sp = &sv.x;
        #pragma unroll
        for (int k = 0; k < 4; k++) {
            if (flags & (1ULL << (i * 4 + k))) {
                float s = sp[k], xx = xp[k];
                float w = fabsf(s);
                float mt = (s < 0.0f) ? xx : -xx;
                if (pos < CAP) { wb[pos] = w; mb[pos] = mt; }
                else if (novf < K_OVF) { ovf_w[novf] = w; ovf_m[novf] = mt; novf++; }
                pos++;
            }
        }
    }
    for (int idx = cnt + r; idx < REG_ELEMS; idx += 16) {
        wb[idx] = 0.0f;
        mb[idx] = 0.0f;
    }
    __syncthreads();

    // ---- Pull 416 elements/row into registers as f32x2 pairs ----
    unsigned long long wreg[PAIRS_REG], xreg[PAIRS_REG];
    {
        const unsigned long long* w64 = reinterpret_cast<const unsigned long long*>(wb);
        const unsigned long long* m64 = reinterpret_cast<const unsigned long long*>(mb);
        #pragma unroll
        for (int i = 0; i < PAIRS_REG; i++) {
            int k = r + 16 * i;
            wreg[i] = w64[k];
            xreg[i] = m64[k];
        }
    }

    const float probe1 = sm[SM_S1S + (r << 5)];
    const unsigned long long ABS2 = 0x7FFFFFFF7FFFFFFFULL;
    const int sCnt = cnt < CAP ? cnt : CAP;
    const bool has_ovf = (cnt > REG_ELEMS);

    float v0 = 0.0f, a0 = 0.0f, v1 = 0.0f, a1 = 0.0f;
    float itf1 = 1.0f;

    for (int t = 0; t < tsteps; t++) {
        const float tf  = itf1 - 1.0f;
        const float inv = rcp_approx(itf1);

        // ---- Speculative new-a0 candidates (bitwise equal to committed update) ----
        float a0_ns = fmaf(a0, tf, 0.0f) * inv;   // no-spike outcome
        float a0_sp = fmaf(a0, tf, 1.0f) * inv;   // spike outcome

        // ---- Speculative layer-1 searches for both candidates (overlap w/ sum) ----
        float cur1_ns, cur1_sp;
        {
            unsigned b1 = __ballot_sync(0xFFFFFFFFu, a1 * probe1 <= a0_ns);
            int cnt1 = __popc(b1 & halfmask);
            int seg = (cnt1 > 0 ? cnt1 - 1 : 0) << 5;
            float p2 = sm[SM_S1S + seg + 2 * r];
            unsigned b2 = __ballot_sync(0xFFFFFFFFu, a1 * p2 <= a0_ns);
            int c2 = __popc(b2 & halfmask);
            int j = seg + 2 * c2 - 1;
            j = j < 0 ? 0 : j;
            int i1 = j + ((a1 * sm[SM_S1S + j] <= a0_ns) ? 1 : 0);
            i1 = (cnt1 == 0) ? 0 : i1;
            float2 pq = pq_sm[i1];
            cur1_ns = fmaf(a0_ns, pq.x, a1 * pq.y);
        }
        {
            unsigned b1 = __ballot_sync(0xFFFFFFFFu, a1 * probe1 <= a0_sp);
            int cnt1 = __popc(b1 & halfmask);
            int seg = (cnt1 > 0 ? cnt1 - 1 : 0) << 5;
            float p2 = sm[SM_S1S + seg + 2 * r];
            unsigned b2 = __ballot_sync(0xFFFFFFFFu, a1 * p2 <= a0_sp);
            int c2 = __popc(b2 & halfmask);
            int j = seg + 2 * c2 - 1;
            j = j < 0 ? 0 : j;
            int i1 = j + ((a1 * sm[SM_S1S + j] <= a0_sp) ? 1 : 0);
            i1 = (cnt1 == 0) ? 0 : i1;
            float2 pq = pq_sm[i1];
            cur1_sp = fmaf(a0_sp, pq.x, a1 * pq.y);
        }

        // ---- Layer 0: cur0 = (2/1024)*(C + a0*D + sum_dyn |w*a0 + mt|) ----
        unsigned long long a0p = pack2(a0, a0);
        unsigned long long acc0 = 0ULL, acc1 = 0ULL;
        #pragma unroll
        for (int i = 0; i < PAIRS_REG - 1; i += 2) {
            acc0 = fadd2(acc0, ffma2(wreg[i],     a0p, xreg[i])     & ABS2);
            acc1 = fadd2(acc1, ffma2(wreg[i + 1], a0p, xreg[i + 1]) & ABS2);
        }
        acc0 = fadd2(acc0, ffma2(wreg[PAIRS_REG - 1], a0p, xreg[PAIRS_REG - 1]) & ABS2);
        float2 f = unpack2(fadd2(acc0, acc1));
        float part = f.x + f.y;

        if (has_ovf) {
            for (int e = REG_ELEMS + r; e < sCnt; e += 16)
                part += fabsf(fmaf(wb[e], a0, mb[e]));
            for (int k = 0; k < novf; k++)
                part += fabsf(fmaf(ovf_w[k], a0, ovf_m[k]));
        }

        #pragma unroll
        for (int o = 8; o; o >>= 1)
            part += __shfl_xor_sync(0xFFFFFFFFu, part, o, 16);

        float cur0 = fmaf(a0, Dv, C + part) * (2.0f / (float)D0);

        // ---- Commit layer 0 and select the speculated layer-1 result ----
        v0 = fmaf(0.5f, v0, cur0);
        bool f0 = (v0 >= 1.0f);
        v0 = f0 ? 0.0f : v0;
        a0 = f0 ? a0_sp : a0_ns;
        float cur1 = f0 ? cur1_sp : cur1_ns;

        v1 = fmaf(0.5f, v1, cur1);
        float sp1 = (v1 >= 1.0f) ? 1.0f : 0.0f;
        v1 = (v1 >= 1.0f) ? 0.0f : v1;
        a1 = fmaf(a1, tf, sp1) * inv;

        itf1 += 1.0f;
    }

    // Output: row = a1 replicated across 256 features (4 float4 per lane)
    float4 o4 = make_float4(a1, a1, a1, a1);
    float4* orow = reinterpret_cast<float4*>(out + (size_t)row * D2);
    #pragma unroll
    for (int q = 0; q < 4; q++) orow[r + 16 * q] = o4;
}

// ---------------------------------------------------------------------------
// Launch
// ---------------------------------------------------------------------------
extern "C" void kernel_launch(void* const* d_in, const int* in_sizes, int n_in,
                              void* d_out, int out_size) {
    const float* x  = (const float*)d_in[0];   // [32768, 1024]
    const float* W0 = (const float*)d_in[1];   // [1024, 512]
    const float* W1 = (const float*)d_in[2];   // [512, 256]
    const int*   ts = (const int*)d_in[3];     // scalar time_steps
    float* out = (float*)d_out;                // [32768, 256]

    const int smem_bytes = SM_FLOATS * 4;      // 67600 B
    cudaFuncSetAttribute(snn_kernel,
                         cudaFuncAttributeMaxDynamicSharedMemorySize, smem_bytes);

    rowsum_kernel<<<192, 256>>>(W0, W1);
    sort_prefix_kernel<<<1, 512>>>();
    snn_kernel<<<BROWS / 16, 256, smem_bytes>>>(x, ts, out);
}